// round 1
// baseline (speedup 1.0000x reference)
#include <cuda_runtime.h>
#include <math.h>

// Device-global accumulators (no allocation allowed).
__device__ double g_sum;     // sum of all 6M distances
__device__ float  g_loss_r;  // regularizer loss

// ---------------------------------------------------------------------------
// Kernel 1: zero accumulator + compute tiny regularizer loss (1 thread).
// ---------------------------------------------------------------------------
__global__ void prep_kernel(const float* __restrict__ planes,  // (3,4)
                            const float* __restrict__ axes)    // (3,4)
{
    g_sum = 0.0;

    // A = n n^T - I, sum(A^2). n rows are planes[:, :3] (NOT normalized).
    float n[3][3];
    #pragma unroll
    for (int i = 0; i < 3; i++)
        #pragma unroll
        for (int c = 0; c < 3; c++)
            n[i][c] = planes[i * 4 + c];

    float sumA2 = 0.f;
    #pragma unroll
    for (int i = 0; i < 3; i++)
        #pragma unroll
        for (int j = 0; j < 3; j++) {
            float dotv = n[i][0] * n[j][0] + n[i][1] * n[j][1] + n[i][2] * n[j][2];
            float a = dotv - (i == j ? 1.f : 0.f);
            sumA2 += a * a;
        }

    // v = normalize(axes[:,1:4]) with max(norm, 1e-12); B = v v^T - I.
    float v[3][3];
    #pragma unroll
    for (int i = 0; i < 3; i++) {
        float x = axes[i * 4 + 1], y = axes[i * 4 + 2], z = axes[i * 4 + 3];
        float nrm = sqrtf(x * x + y * y + z * z);
        float inv = 1.f / fmaxf(nrm, 1e-12f);
        v[i][0] = x * inv; v[i][1] = y * inv; v[i][2] = z * inv;
    }
    float sumB2 = 0.f;
    #pragma unroll
    for (int i = 0; i < 3; i++)
        #pragma unroll
        for (int j = 0; j < 3; j++) {
            float dotv = v[i][0] * v[j][0] + v[i][1] * v[j][1] + v[i][2] * v[j][2];
            float b = dotv - (i == j ? 1.f : 0.f);
            sumB2 += b * b;
        }

    g_loss_r = sumA2 + sumB2;
}

// ---------------------------------------------------------------------------
// Grid distance helper: nearest grid cell (round-half-even like jnp.round),
// clamp to [0, R-1], gather 3 floats, return |tp - cp|.
// ---------------------------------------------------------------------------
__device__ __forceinline__ float grid_dist(float tx, float ty, float tz,
                                           const float* __restrict__ grid,
                                           float gx, float gy, float gz,   // grid_min
                                           float sx, float sy, float sz,   // (R-1)/(max-min)
                                           int R)
{
    float fx = (tx - gx) * sx;
    float fy = (ty - gy) * sy;
    float fz = (tz - gz) * sz;
    int ix = (int)fminf(fmaxf(rintf(fx), 0.f), (float)(R - 1));
    int iy = (int)fminf(fmaxf(rintf(fy), 0.f), (float)(R - 1));
    int iz = (int)fminf(fmaxf(rintf(fz), 0.f), (float)(R - 1));
    long off = (((long)ix * R + iy) * R + iz) * 3;
    float cx = __ldg(grid + off);
    float cy = __ldg(grid + off + 1);
    float cz = __ldg(grid + off + 2);
    float dx = tx - cx, dy = ty - cy, dz = tz - cz;
    return sqrtf(dx * dx + dy * dy + dz * dz);
}

// ---------------------------------------------------------------------------
// Kernel 2: per-point work. 1 point/thread, 6 transforms + gathers, reduce.
// ---------------------------------------------------------------------------
__global__ void __launch_bounds__(256)
main_kernel(const float* __restrict__ pts,
            const float* __restrict__ planes,
            const float* __restrict__ axes,
            const float* __restrict__ grid,
            const float* __restrict__ gmin,
            const float* __restrict__ gmax,
            int N, int R)
{
    int i = blockIdx.x * blockDim.x + threadIdx.x;

    float gx = __ldg(gmin), gy = __ldg(gmin + 1), gz = __ldg(gmin + 2);
    float sx = (float)(R - 1) / (__ldg(gmax) - gx);
    float sy = (float)(R - 1) / (__ldg(gmax + 1) - gy);
    float sz = (float)(R - 1) / (__ldg(gmax + 2) - gz);

    float local = 0.f;

    if (i < N) {
        float px = __ldg(pts + 3 * i);
        float py = __ldg(pts + 3 * i + 1);
        float pz = __ldg(pts + 3 * i + 2);

        // Plane reflections
        #pragma unroll
        for (int k = 0; k < 3; k++) {
            float nx = __ldg(planes + k * 4);
            float ny = __ldg(planes + k * 4 + 1);
            float nz = __ldg(planes + k * 4 + 2);
            float d  = __ldg(planes + k * 4 + 3);
            float proj = px * nx + py * ny + pz * nz + d;
            float rx = px - 2.f * proj * nx;
            float ry = py - 2.f * proj * ny;
            float rz = pz - 2.f * proj * nz;
            local += grid_dist(rx, ry, rz, grid, gx, gy, gz, sx, sy, sz, R);
        }

        // Quaternion rotations (q NOT normalized — matches reference)
        #pragma unroll
        for (int k = 0; k < 3; k++) {
            float w = __ldg(axes + k * 4);
            float x = __ldg(axes + k * 4 + 1);
            float y = __ldg(axes + k * 4 + 2);
            float z = __ldg(axes + k * 4 + 3);
            // t = q * (0, p)
            float tw = -x * px - y * py - z * pz;
            float tx =  w * px + y * pz - z * py;
            float ty =  w * py - x * pz + z * px;
            float tz =  w * pz + x * py - y * px;
            // r = t * conj(q), vector part
            float rx = -tw * x + tx * w - ty * z + tz * y;
            float ry = -tw * y + tx * z + ty * w - tz * x;
            float rz = -tw * z - tx * y + ty * x + tz * w;
            local += grid_dist(rx, ry, rz, grid, gx, gy, gz, sx, sy, sz, R);
        }
    }

    // Warp reduce
    #pragma unroll
    for (int off = 16; off > 0; off >>= 1)
        local += __shfl_down_sync(0xFFFFFFFFu, local, off);

    // Block reduce
    __shared__ float warp_sums[8];
    int lane = threadIdx.x & 31;
    int wid  = threadIdx.x >> 5;
    if (lane == 0) warp_sums[wid] = local;
    __syncthreads();
    if (wid == 0) {
        float s = (lane < (blockDim.x >> 5)) ? warp_sums[lane] : 0.f;
        #pragma unroll
        for (int off = 4; off > 0; off >>= 1)
            s += __shfl_down_sync(0xFFFFFFFFu, s, off);
        if (lane == 0)
            atomicAdd(&g_sum, (double)s);
    }
}

// ---------------------------------------------------------------------------
// Kernel 3: finalize (1 thread).
// ---------------------------------------------------------------------------
__global__ void finalize_kernel(float* __restrict__ out, int out_size, int N)
{
    float sd = (float)(g_sum / (double)N);
    float r  = g_loss_r;
    float fin = sd + 25.0f * r;
    out[0] = fin;
    if (out_size > 1) out[1] = sd;
    if (out_size > 2) out[2] = r;
}

// ---------------------------------------------------------------------------
extern "C" void kernel_launch(void* const* d_in, const int* in_sizes, int n_in,
                              void* d_out, int out_size)
{
    const float* planes = (const float*)d_in[0];   // (1,3,4)
    const float* axes   = (const float*)d_in[1];   // (1,3,4)
    const float* pts    = (const float*)d_in[2];   // (N,3)
    const float* grid   = (const float*)d_in[3];   // (R,R,R,3)
    const float* gmin   = (const float*)d_in[4];   // (3,)
    const float* gmax   = (const float*)d_in[5];   // (3,)

    int N = in_sizes[2] / 3;
    // R from grid element count = R^3 * 3
    long gelems = (long)in_sizes[3] / 3;
    int R = (int)llrintf(cbrtf((float)gelems));

    prep_kernel<<<1, 1>>>(planes, axes);

    int threads = 256;
    int blocks = (N + threads - 1) / threads;
    main_kernel<<<blocks, threads>>>(pts, planes, axes, grid, gmin, gmax, N, R);

    finalize_kernel<<<1, 1>>>((float*)d_out, out_size, N);
}